// round 1
// baseline (speedup 1.0000x reference)
#include <cuda_runtime.h>
#include <math.h>

// Equivariant tensor-product conv, restructured:
//   S[H=65, C=224] = sum_b h~(r_zab) (outer) G(n_zab, f_zb)
//   out[z,a,:] = W2~ (contract H) S (contract paths)
// G columns: [0:16) g0 | [16:32) g1 | [32:80) g2(i,v) | [80:128) g3_lf0 |
//            [128:176) g3_lf1 | [176:224) g3_lf2   (each (i,v) block = i*16+v)

__global__ void __launch_bounds__(256, 2)
conv_kernel(const float* __restrict__ feat,
            const float* __restrict__ geo,
            const float* __restrict__ maskp,
            const float* __restrict__ W1,
            const float* __restrict__ b1,
            const float* __restrict__ W2,
            const float* __restrict__ b2,
            float* __restrict__ out)
{
    constexpr int A = 160, B = 160, DIM = 64;
    constexpr int CHUNK = 16;
    // spherical-harmonic / wigner / norm constants (derived analytically)
    constexpr float C0   = 0.28209479177387814f;   // Y00
    constexpr float NC00 = 0.6266570686577501f;    // sqrt(4pi)/sqrt(32)
    constexpr float NC01 = 1.0854018854473597f;    // sqrt(3)*sqrt(4pi)/sqrt(32)
    constexpr float NC10 = 0.4431134627263790f;    // sqrt(4pi)/8
    constexpr float NC11 = 0.7674950356098778f;    // sqrt(3)*sqrt(4pi)/8
    constexpr float NCZ0 = 0.8862269254527580f;    // r==0: sqrt(4pi)/4
    constexpr float NCZ1 = 1.5349900712197556f;    // r==0: sqrt(3)*sqrt(4pi)/4
    constexpr float E1   = 0.19947114020071635f;   // c1/sqrt(6)  (l_f=1 cross term)
    constexpr float AL   = 0.34549414947133547f;   // sqrt(3/(8pi)) (l_f=2 term)
    constexpr float C0S3 = 0.16286750396763996f;   // c0/sqrt(3)  (l_f=0 term)
    constexpr float QZ   = 0.05758236f;            // c2/sqrt(30) (r==0, l_f=2)

    extern __shared__ float sm[];
    float* g_sh = sm;              // [16][224] phase-1 G staging
    float* h_sh = sm + 16 * 224;   // [16][72]  phase-1 h staging (rows 65..71 zeroed)
    float* S_sh = sm;              // [65][225] phase-2 (overlaps dead g/h buffers)
    float* w1s  = sm + 14656;      // [64]
    float* b1s  = sm + 14720;      // [64]

    const int a  = blockIdx.x, z = blockIdx.y;
    const int tid = threadIdx.x;
    if (tid < 64) { w1s[tid] = W1[tid]; b1s[tid] = b1[tid]; }
    __syncthreads();

    const int ty = tid >> 5, tx = tid & 31;   // S tile: H = ty+8m, col = tx+32q
    float S[9][7];
    #pragma unroll
    for (int m = 0; m < 9; m++)
        #pragma unroll
        for (int q = 0; q < 7; q++) S[m][q] = 0.0f;

    const int bl = tid >> 4, vv = tid & 15;   // G builder: 16 threads per b
    const float* geoA = geo + (size_t)((z * A + a) * B) * 3;
    const float* fz   = feat + (size_t)z * B * DIM;

    for (int b0 = 0; b0 < B; b0 += CHUNK) {
        const int b = b0 + bl;
        // direction + radius (matches jnp: n = xyz / where(r>0, r, 1))
        const float gx = geoA[b * 3 + 0];
        const float gy = geoA[b * 3 + 1];
        const float gz = geoA[b * 3 + 2];
        const float r  = sqrtf(gx * gx + gy * gy + gz * gz);
        const bool  is0 = (r == 0.0f);
        const float inv = is0 ? 1.0f : (1.0f / r);
        const float v0 = gy * inv, v1 = gz * inv, v2 = gx * inv; // (y,z,x) SH order

        // h~ = [relu(r*W1+b1), 1, 0-pad]
        float* hrow = h_sh + bl * 72;
        #pragma unroll
        for (int m = 0; m < 4; m++) {
            const int hh = vv + 16 * m;
            hrow[hh] = fmaxf(fmaf(r, w1s[hh], b1s[hh]), 0.0f);
        }
        if (vv == 0) hrow[64] = 1.0f;
        else if (vv <= 7) hrow[64 + vv] = 0.0f;

        const float ncA = is0 ? NCZ0 : NC00;
        const float ncB = is0 ? NCZ1 : NC01;
        const float ncC = is0 ? NCZ0 : NC10;
        const float ncD = is0 ? NCZ1 : NC11;

        const float* f = fz + b * DIM;
        const float f0v = f[vv];
        const float p0 = f[16 + 3 * vv], p1 = f[17 + 3 * vv], p2 = f[18 + 3 * vv];
        const float s  = v0 * p0 + v1 * p1 + v2 * p2;

        float* G = g_sh + bl * 224;
        G[vv]       = ncA * C0 * f0v;                 // path (l0<-l0, lf=0)
        G[16 + vv]  = ncB * C0 * s;                   // path (l0<-l1, lf=1)
        const float t2 = ncC * C0 * f0v;              // path (l1<-l0, lf=1)
        G[32 + vv]  = t2 * v0;
        G[48 + vv]  = t2 * v1;
        G[64 + vv]  = t2 * v2;
        const float t3a = ncD * C0S3;                 // path (l1<-l1, lf=0)
        G[80 + vv]  = t3a * p0;
        G[96 + vv]  = t3a * p1;
        G[112 + vv] = t3a * p2;
        const float t3b = ncD * E1;                   // path (l1<-l1, lf=1): +eps/sqrt6
        G[128 + vv] = t3b * (p1 * v2 - p2 * v1);      // (f1 x v)
        G[144 + vv] = t3b * (p2 * v0 - p0 * v2);
        G[160 + vv] = t3b * (p0 * v1 - p1 * v0);
        if (!is0) {                                   // path (l1<-l1, lf=2)
            const float t3c = ncD * AL;
            G[176 + vv] = t3c * (v0 * s - p0 * (1.0f / 3.0f));
            G[192 + vv] = t3c * (v1 * s - p1 * (1.0f / 3.0f));
            G[208 + vv] = t3c * (v2 * s - p2 * (1.0f / 3.0f));
        } else {                                      // Y2(0) = (0,0,-c2,0,0)
            const float q = ncD * QZ;
            G[176 + vv] = q * p0;
            G[192 + vv] = -2.0f * q * p1;
            G[208 + vv] = q * p2;
        }
        __syncthreads();

        // rank-16 update of S (outer products h~ x G)
        #pragma unroll 4
        for (int j = 0; j < CHUNK; j++) {
            float hv[9], gv[7];
            #pragma unroll
            for (int m = 0; m < 9; m++) hv[m] = h_sh[j * 72 + ty + 8 * m];   // bcast
            #pragma unroll
            for (int q = 0; q < 7; q++) gv[q] = g_sh[j * 224 + tx + 32 * q]; // no-conflict
            #pragma unroll
            for (int m = 0; m < 9; m++)
                #pragma unroll
                for (int q = 0; q < 7; q++)
                    S[m][q] = fmaf(hv[m], gv[q], S[m][q]);
        }
        __syncthreads();
    }

    // spill S to shared (stride 225 to dodge bank conflicts in phase 2)
    #pragma unroll
    for (int m = 0; m < 9; m++) {
        const int hh = ty + 8 * m;
        if (hh <= 64) {
            #pragma unroll
            for (int q = 0; q < 7; q++)
                S_sh[hh * 225 + tx + 32 * q] = S[m][q];
        }
    }
    __syncthreads();

    // phase 2: out[oi] = sum_H sum_cols W2~[H,col(oi)] * S[H,col]
    // 4 threads per output split the H range; part 0 also takes H=64 (b2 row)
    const int oi = tid >> 2, part = tid & 3;
    float acc = 0.0f;
    const int hcnt = (part == 0) ? 17 : 16;
    if (oi < 16) {                                    // l=0 outputs: cols u*16+v, 256+u*16+v
        const int u = oi;
        for (int t = 0; t < hcnt; t++) {
            const int hh = (t == 16) ? 64 : part * 16 + t;
            const float* w  = (hh == 64) ? b2 : (W2 + hh * 1536);
            const float* Sr = S_sh + hh * 225;
            #pragma unroll
            for (int v = 0; v < 16; v++) {
                acc = fmaf(w[u * 16 + v],        Sr[v],      acc);
                acc = fmaf(w[256 + u * 16 + v],  Sr[16 + v], acc);
            }
        }
    } else {                                          // l=1 outputs (u,i)
        const int qq = oi - 16;
        const int u  = qq / 3;
        const int i  = qq - 3 * u;
        for (int t = 0; t < hcnt; t++) {
            const int hh = (t == 16) ? 64 : part * 16 + t;
            const float* w  = (hh == 64) ? b2 : (W2 + hh * 1536);
            const float* Sr = S_sh + hh * 225;
            #pragma unroll
            for (int v = 0; v < 16; v++) {
                acc = fmaf(w[512 + u * 16 + v], Sr[32 + i * 16 + v], acc);
                const float* wb = w + 768 + (u * 16 + v) * 3;
                acc = fmaf(wb[0], Sr[80  + i * 16 + v], acc);
                acc = fmaf(wb[1], Sr[128 + i * 16 + v], acc);
                acc = fmaf(wb[2], Sr[176 + i * 16 + v], acc);
            }
        }
    }
    // reduce the 4 H-parts (consecutive lanes)
    acc += __shfl_down_sync(0xffffffffu, acc, 1);
    acc += __shfl_down_sync(0xffffffffu, acc, 2);
    if (part == 0) {
        const float mv = maskp[z * A + a];   // mask (batch,b) broadcast over a (a==b)
        out[(size_t)((z * A + a) * DIM) + oi] = acc * mv;
    }
}

extern "C" void kernel_launch(void* const* d_in, const int* in_sizes, int n_in,
                              void* d_out, int out_size)
{
    const float* feat  = (const float*)d_in[0];
    const float* geo   = (const float*)d_in[1];
    const float* maskp = (const float*)d_in[2];
    const float* W1    = (const float*)d_in[3];
    const float* b1    = (const float*)d_in[4];
    const float* W2    = (const float*)d_in[5];
    const float* b2    = (const float*)d_in[6];
    float* out = (float*)d_out;

    const int smem_bytes = 14784 * 4;  // 59,136 B: max(G+h, S) + W1/b1 stash
    cudaFuncSetAttribute(conv_kernel, cudaFuncAttributeMaxDynamicSharedMemorySize,
                         smem_bytes);
    dim3 grid(160, 2);
    conv_kernel<<<grid, 256, smem_bytes>>>(feat, geo, maskp, W1, b1, W2, b2, out);
}